// round 8
// baseline (speedup 1.0000x reference)
#include <cuda_runtime.h>
#include <cstdint>

#define BATCH   32
#define NA      9
#define HW      4096
#define NPROP   (HW*NA)          // 36864
#define NVEC    (NPROP/4)        // 9216 float4 per batch
#define TOPK    300
#define OUTC    66
#define CAP     2048
#define LCAP    1024             // per-CTA staging capacity
#define NCTAS   148              // exactly one wave: spins are deadlock-free
#define CHUNKS  10               // ceil(300/32) decode chunks per batch
#define NITEMS  (BATCH*CHUNKS)   // 320

// key threshold for score >= 2.0f (~840 candidates/batch expected; 210/CTA)
#define THR_FAST 0xC0000000u

// Anchor (w,h) table; centers are always (8+16*gx, 8+16*gy)
__constant__ float c_aw[9] = {92.f,184.f,368.f,64.f,128.f,256.f,44.f,88.f,176.f};
__constant__ float c_ah[9] = {48.f,96.f,192.f,64.f,128.f,256.f,88.f,176.f,352.f};

__device__ int                g_cnt[BATCH * 32];     // stride-32: 128B apart
__device__ int                g_done[BATCH * 32];
__device__ volatile int       g_ready[BATCH];
__device__ int                g_fin;
__device__ unsigned long long g_cand[BATCH * CAP];
__device__ unsigned           g_dec[BATCH * TOPK];   // n | (rank<<16), asc n

__device__ __forceinline__ unsigned f2key(float s) {
    unsigned u = __float_as_uint(s);
    return (u & 0x80000000u) ? ~u : (u | 0x80000000u);
}

__global__ __launch_bounds__(1024, 1)
void fused_kernel(const float* __restrict__ scores_in,
                  const float* __restrict__ bbox,
                  const float* __restrict__ im_info,
                  float* __restrict__ out)
{
    __shared__ unsigned long long buf[LCAP];     // 8 KB  (compact staging)
    __shared__ unsigned long long cand[CAP];     // 16 KB (rank)
    __shared__ unsigned hist[4096];              // 16 KB (fallback only)
    __shared__ unsigned sel_n[TOPK];
    __shared__ unsigned wsum[32], wpre[32];
    __shared__ unsigned s_thr;
    __shared__ int s_cnt, s_base, s_C, s_isrank;

    const int c   = blockIdx.x;
    const int tid = threadIdx.x;
    const unsigned lane = tid & 31u;
    const int warp = tid >> 5;

    // ===================== Phase 1: compact (CTAs 0..127) =====================
    if (c < 4 * BATCH) {
        const int b = c >> 2, slice = c & 3;
        const float4* sp =
            (const float4*)(scores_in + (size_t)b * 18 * HW + (size_t)NA * HW);

        if (tid == 0) s_cnt = 0;
        __syncthreads();

        for (int i = slice * 1024 + tid; i < NVEC; i += 4096) {
            float4 v = sp[i];
            float vv[4] = {v.x, v.y, v.z, v.w};
            #pragma unroll
            for (int j = 0; j < 4; j++) {
                unsigned k = f2key(vv[j]);
                if (k >= THR_FAST) {
                    int idx = 4 * i + j;            // memory order: a*4096 + hw
                    int a = idx >> 12, hw = idx & 4095;
                    int n = hw * 9 + a;             // jax flat order
                    int pos = atomicAdd(&s_cnt, 1); // smem atomic: cheap
                    if (pos < LCAP)
                        buf[pos] = ((unsigned long long)k << 32) | (unsigned)(~n);
                }
            }
        }
        __syncthreads();

        const int cnt = s_cnt;
        if (cnt > LCAP) {
            // staging overflow (benign-impossible): poison count -> fallback
            if (tid == 0) atomicAdd(&g_cnt[b * 32], CAP + 1);
        } else {
            if (tid == 0) s_base = atomicAdd(&g_cnt[b * 32], cnt); // ONE RMW
            __syncthreads();
            for (int i = tid; i < cnt; i += 1024) {
                int pos = s_base + i;
                if (pos < CAP) g_cand[b * CAP + pos] = buf[i];
            }
        }
        __threadfence();                 // each thread publishes its writes
        __syncthreads();
        if (tid == 0) {
            int t = atomicAdd(&g_done[b * 32], 1);
            s_isrank = (t == 3);         // 4th finisher ranks this batch
        }
        __syncthreads();

        // ===================== Phase 2: rank (32 elected CTAs) ================
        if (s_isrank) {
            __threadfence();             // acquire other compacters' writes
            if (tid == 0) s_C = g_cnt[b * 32];
            __syncthreads();
            int C = s_C;
            if (tid == 0) { g_cnt[b * 32] = 0; g_done[b * 32] = 0; } // replay reset

            const float4* sp =
                (const float4*)(scores_in + (size_t)b * 18 * HW + (size_t)NA * HW);

            if (C >= TOPK && C <= CAP) {
                for (int i = tid; i < C; i += 1024)
                    cand[i] = g_cand[b * CAP + i];
                __syncthreads();
            } else {
                // ---- exact fallback: 4096-bin histogram select ----
                #pragma unroll
                for (int i = tid; i < 4096; i += 1024) hist[i] = 0;
                if (tid == 0) s_cnt = 0;
                __syncthreads();
                #pragma unroll 3
                for (int i = tid; i < NVEC; i += 1024) {
                    float4 v = sp[i];
                    atomicAdd(&hist[f2key(v.x) >> 20], 1u);
                    atomicAdd(&hist[f2key(v.y) >> 20], 1u);
                    atomicAdd(&hist[f2key(v.z) >> 20], 1u);
                    atomicAdd(&hist[f2key(v.w) >> 20], 1u);
                }
                __syncthreads();
                const int bhi = 4095 - 4 * tid;
                unsigned h0 = hist[bhi],     h1 = hist[bhi - 1];
                unsigned h2 = hist[bhi - 2], h3 = hist[bhi - 3];
                unsigned s = h0 + h1 + h2 + h3;
                unsigned incl = s;
                #pragma unroll
                for (int o = 1; o < 32; o <<= 1) {
                    unsigned v = __shfl_up_sync(0xFFFFFFFFu, incl, o);
                    if (lane >= o) incl += v;
                }
                if (lane == 31) wsum[warp] = incl;
                __syncthreads();
                if (warp == 0) {
                    unsigned w = wsum[lane];
                    unsigned wi = w;
                    #pragma unroll
                    for (int o = 1; o < 32; o <<= 1) {
                        unsigned v = __shfl_up_sync(0xFFFFFFFFu, wi, o);
                        if (lane >= o) wi += v;
                    }
                    wpre[lane] = wi - w;
                }
                __syncthreads();
                {
                    unsigned cc = wpre[warp] + (incl - s);
                    unsigned hh[4] = {h0, h1, h2, h3};
                    #pragma unroll
                    for (int j = 0; j < 4; j++) {
                        if (cc < TOPK && cc + hh[j] >= TOPK)
                            s_thr = ((unsigned)(bhi - j)) << 20;
                        cc += hh[j];
                    }
                }
                __syncthreads();
                const unsigned thr = s_thr;
                #pragma unroll 3
                for (int i = tid; i < NVEC; i += 1024) {
                    float4 v = sp[i];
                    float vv[4] = {v.x, v.y, v.z, v.w};
                    #pragma unroll
                    for (int j = 0; j < 4; j++) {
                        unsigned k = f2key(vv[j]);
                        if (k >= thr) {
                            int idx = 4 * i + j;
                            int a = idx >> 12, hw = idx & 4095;
                            int n = hw * 9 + a;
                            int pos = atomicAdd(&s_cnt, 1);
                            if (pos < CAP)
                                cand[pos] = ((unsigned long long)k << 32)
                                            | (unsigned)(~n);
                        }
                    }
                }
                __syncthreads();
                C = min(s_cnt, CAP);
            }

            // exact rank by counting (unique keys -> jax tie-break preserved)
            for (int i = tid; i < C; i += 1024) {
                const unsigned long long me = cand[i];
                int r = 0;
                for (int j = 0; j < C; j++) r += (cand[j] > me);
                if (r < TOPK) {
                    unsigned n = (unsigned)(~(unsigned)me) & 0xFFFFu;
                    sel_n[r] = n;
                    unsigned k32 = (unsigned)(me >> 32);
                    unsigned u = (k32 & 0x80000000u) ? (k32 & 0x7FFFFFFFu) : ~k32;
                    size_t row = ((size_t)b * TOPK + r) * OUTC;
                    out[row + 0] = (float)b;
                    out[row + OUTC - 1] = __uint_as_float(u);
                }
            }
            __syncthreads();

            // decode feed in ascending flat-index order (gather locality)
            if (tid < TOPK) {
                unsigned n = sel_n[tid];
                int o = 0;
                for (int j = 0; j < TOPK; j++) o += (sel_n[j] < n);
                g_dec[b * TOPK + o] = n | ((unsigned)tid << 16);
            }
            __threadfence();             // publish g_dec + out before flag
            __syncthreads();
            if (tid == 0) atomicExch((int*)(g_ready + b), 1);
        }
    }

    // ===================== Phase 3: decode (ALL 148 CTAs) =====================
    const int g = tid >> 6;              // group 0..15 (2 warps, warp-uniform)
    const int k = tid & 63;
    const unsigned base = (tid & 31u) & ~3u;

    for (int it = c; it < NITEMS; it += NCTAS) {
        const int b = it / CHUNKS;
        const int chunk = it % CHUNKS;

        if (tid == 0) { while (g_ready[b] == 0) __nanosleep(128); }
        __syncthreads();
        __threadfence();                 // acquire producer writes

        const float xmax = im_info[b * 3 + 1] - 1.0f;
        const float ymax = im_info[b * 3 + 0] - 1.0f;

        const int p0 = chunk * 32 + g * 2;
        const int p1 = p0 + 1;
        const bool v0 = p0 < TOPK, v1 = p1 < TOPK;   // uniform per 64-group

        const unsigned pk0 = g_dec[b * TOPK + (v0 ? p0 : 0)];
        const unsigned pk1 = g_dec[b * TOPK + (v1 ? p1 : 0)];

        const int n0 = pk0 & 0xFFFFu, n1 = pk1 & 0xFFFFu;
        const int a0 = n0 % 9, hw0 = n0 / 9;
        const int a1 = n1 % 9, hw1 = n1 / 9;

        // two independent scattered loads -> MLP 2
        const float dd0 = __ldcs(&bbox[((size_t)b * 576 + a0 * 64 + k) * HW + hw0]);
        const float dd1 = __ldcs(&bbox[((size_t)b * 576 + a1 * 64 + k) * HW + hw1]);

        #pragma unroll
        for (int q = 0; q < 2; q++) {
            const float dd = q ? dd1 : dd0;
            const int a  = q ? a1 : a0;
            const int hw = q ? hw1 : hw0;
            const int rank = (q ? pk1 : pk0) >> 16;
            const bool vld = q ? v1 : v0;

            const float w  = c_aw[a];
            const float h  = c_ah[a];
            const float cx = 8.0f + 16.0f * (float)(hw & 63);
            const float cy = 8.0f + 16.0f * (float)(hw >> 6);

            const float d0 = __shfl_sync(0xFFFFFFFFu, dd, base + 0);
            const float d1 = __shfl_sync(0xFFFFFFFFu, dd, base + 1);
            const float d2 = __shfl_sync(0xFFFFFFFFu, dd, base + 2);
            const float d3 = __shfl_sync(0xFFFFFFFFu, dd, base + 3);

            const float pcx = d0 * w + cx;
            const float pcy = d1 * h + cy;
            const float pw  = expf(d2) * w;
            const float ph  = expf(d3) * h;

            float v;
            switch (k & 3) {
                case 0: v = fminf(fmaxf(pcx - 0.5f * pw, 0.0f), xmax); break;
                case 1: v = fminf(fmaxf(pcy - 0.5f * ph, 0.0f), ymax); break;
                case 2: v = fminf(fmaxf(pcx + 0.5f * pw, 0.0f), xmax); break;
                default: v = fminf(fmaxf(pcy + 0.5f * ph, 0.0f), ymax); break;
            }
            if (vld)
                out[((size_t)b * TOPK + rank) * OUTC + 1 + k] = v;
        }
    }

    // ===================== Epilogue: replay reset =====================
    __threadfence();
    __syncthreads();
    if (tid == 0) {
        int t = atomicAdd(&g_fin, 1);
        if (t == NCTAS - 1) {            // last CTA: nobody reads these anymore
            for (int i = 0; i < BATCH; i++) *(int*)(g_ready + i) = 0;
            g_fin = 0;
            __threadfence();
        }
    }
}

extern "C" void kernel_launch(void* const* d_in, const int* in_sizes, int n_in,
                              void* d_out, int out_size)
{
    const float* scores  = (const float*)d_in[0];  // (32,18,64,64)
    const float* bbox    = (const float*)d_in[1];  // (32,576,64,64)
    const float* im_info = (const float*)d_in[2];  // (32,3)
    float* out = (float*)d_out;                    // (32,300,66)

    fused_kernel<<<NCTAS, 1024>>>(scores, bbox, im_info, out);
}

// round 9
// speedup vs baseline: 1.0073x; 1.0073x over previous
#include <cuda_runtime.h>
#include <cstdint>

#define BATCH   32
#define NA      9
#define HW      4096
#define NPROP   (HW*NA)          // 36864
#define NVEC    (NPROP/4)        // 9216 float4 per batch
#define TOPK    300
#define OUTC    66
#define CAP     2048
#define LCAP    768              // per-CTA staging (expect ~210)
#define SLICES  4                // compact CTAs per batch

// key threshold for score >= 2.0f (~840 candidates/batch expected)
#define THR_FAST 0xC0000000u

// Anchor (w,h) table; centers are always (8+16*gx, 8+16*gy)
__constant__ float c_aw[9] = {92.f,184.f,368.f,64.f,128.f,256.f,44.f,88.f,176.f};
__constant__ float c_ah[9] = {48.f,96.f,192.f,64.f,128.f,256.f,88.f,176.f,352.f};

__device__ int                g_cnt[BATCH * 32];   // stride-32: 128B apart
__device__ int                g_done[BATCH * 32];
__device__ unsigned long long g_cand[BATCH * CAP];
__device__ unsigned           g_dec[BATCH * TOPK]; // n | (rank<<16), asc n

__device__ __forceinline__ unsigned f2key(float s) {
    unsigned u = __float_as_uint(s);
    return (u & 0x80000000u) ? ~u : (u | 0x80000000u);
}

// ---------------------------------------------------------------------------
// Kernel 1: compact (all 128 CTAs) + rank (last-finishing CTA per batch).
// No spin-waits: the ranking CTA is elected as the LAST compact finisher.
// ---------------------------------------------------------------------------
__global__ __launch_bounds__(512, 1)
void topk_kernel(const float* __restrict__ scores_in, float* __restrict__ out)
{
    __shared__ unsigned long long buf[LCAP];     // 6 KB  (compact staging)
    __shared__ unsigned long long cand[CAP];     // 16 KB (rank)
    __shared__ unsigned hist[4096];              // 16 KB (fallback only)
    __shared__ unsigned sel_n[TOPK];
    __shared__ unsigned wsum[16], wpre[16];
    __shared__ unsigned s_thr;
    __shared__ int s_cnt, s_base, s_C, s_isrank;

    const int b     = blockIdx.y;
    const int slice = blockIdx.x;
    const int tid   = threadIdx.x;
    const unsigned lane = tid & 31u;
    const int warp  = tid >> 5;

    const float4* sp =
        (const float4*)(scores_in + (size_t)b * 18 * HW + (size_t)NA * HW);

    // ---------------- compact: smem staging, one global RMW ----------------
    if (tid == 0) s_cnt = 0;
    __syncthreads();

    for (int i = slice * 512 + tid; i < NVEC; i += SLICES * 512) {
        float4 v = sp[i];
        float vv[4] = {v.x, v.y, v.z, v.w};
        #pragma unroll
        for (int j = 0; j < 4; j++) {
            unsigned k = f2key(vv[j]);
            if (k >= THR_FAST) {
                int idx = 4 * i + j;               // memory order: a*4096 + hw
                int a = idx >> 12, hw = idx & 4095;
                int n = hw * 9 + a;                // jax flat order
                int pos = atomicAdd(&s_cnt, 1);    // smem atomic: cheap
                if (pos < LCAP)
                    buf[pos] = ((unsigned long long)k << 32) | (unsigned)(~n);
            }
        }
    }
    __syncthreads();

    const int cnt = s_cnt;
    if (cnt > LCAP) {
        // staging overflow (benign-impossible): poison count -> exact fallback
        if (tid == 0) atomicAdd(&g_cnt[b * 32], CAP + 1);
    } else {
        if (tid == 0) s_base = atomicAdd(&g_cnt[b * 32], cnt);  // ONE RMW
        __syncthreads();
        for (int i = tid; i < cnt; i += 512) {
            int pos = s_base + i;
            if (pos < CAP) g_cand[b * CAP + pos] = buf[i];
        }
    }
    __threadfence();                  // publish this CTA's candidate writes
    __syncthreads();
    if (tid == 0) {
        int t = atomicAdd(&g_done[b * 32], 1);
        s_isrank = (t == SLICES - 1); // last finisher ranks this batch
    }
    __syncthreads();
    if (!s_isrank) return;

    // ---------------- rank (elected CTA; all peers already done) ----------
    __threadfence();                  // acquire peers' g_cand writes
    if (tid == 0) s_C = g_cnt[b * 32];
    __syncthreads();
    int C = s_C;
    if (tid == 0) { g_cnt[b * 32] = 0; g_done[b * 32] = 0; }   // replay reset

    if (C >= TOPK && C <= CAP) {
        for (int i = tid; i < C; i += 512)
            cand[i] = g_cand[b * CAP + i];
        __syncthreads();
    } else {
        // ---- exact fallback: 4096-bin histogram select (512 threads) ----
        #pragma unroll
        for (int i = tid; i < 4096; i += 512) hist[i] = 0;
        if (tid == 0) s_cnt = 0;
        __syncthreads();
        for (int i = tid; i < NVEC; i += 512) {
            float4 v = sp[i];
            atomicAdd(&hist[f2key(v.x) >> 20], 1u);
            atomicAdd(&hist[f2key(v.y) >> 20], 1u);
            atomicAdd(&hist[f2key(v.z) >> 20], 1u);
            atomicAdd(&hist[f2key(v.w) >> 20], 1u);
        }
        __syncthreads();
        // suffix scan from the top: thread t owns bins [4095-8t .. 4088-8t]
        const int bhi = 4095 - 8 * tid;
        unsigned hh[8];
        unsigned s = 0;
        #pragma unroll
        for (int j = 0; j < 8; j++) { hh[j] = hist[bhi - j]; s += hh[j]; }
        unsigned incl = s;
        #pragma unroll
        for (int o = 1; o < 32; o <<= 1) {
            unsigned v = __shfl_up_sync(0xFFFFFFFFu, incl, o);
            if (lane >= o) incl += v;
        }
        if (lane == 31) wsum[warp] = incl;
        __syncthreads();
        if (warp == 0 && lane < 16) {
            unsigned w = wsum[lane];
            unsigned wi = w;
            #pragma unroll
            for (int o = 1; o < 16; o <<= 1) {
                unsigned v = __shfl_up_sync(0xFFFFu, wi, o);
                if (lane >= o) wi += v;
            }
            wpre[lane] = wi - w;
        }
        __syncthreads();
        {
            unsigned cc = wpre[warp] + (incl - s);   // above bin bhi
            #pragma unroll
            for (int j = 0; j < 8; j++) {
                if (cc < TOPK && cc + hh[j] >= TOPK)
                    s_thr = ((unsigned)(bhi - j)) << 20;
                cc += hh[j];
            }
        }
        __syncthreads();
        const unsigned thr = s_thr;
        for (int i = tid; i < NVEC; i += 512) {
            float4 v = sp[i];
            float vv[4] = {v.x, v.y, v.z, v.w};
            #pragma unroll
            for (int j = 0; j < 4; j++) {
                unsigned k = f2key(vv[j]);
                if (k >= thr) {
                    int idx = 4 * i + j;
                    int a = idx >> 12, hw = idx & 4095;
                    int n = hw * 9 + a;
                    int pos = atomicAdd(&s_cnt, 1);
                    if (pos < CAP)
                        cand[pos] = ((unsigned long long)k << 32) | (unsigned)(~n);
                }
            }
        }
        __syncthreads();
        C = min(s_cnt, CAP);
    }

    // ---- exact rank by counting (unique keys -> jax tie-break preserved) ----
    for (int i = tid; i < C; i += 512) {
        const unsigned long long me = cand[i];
        int r = 0;
        for (int j = 0; j < C; j++) r += (cand[j] > me);   // smem broadcast
        if (r < TOPK) {
            unsigned n = (unsigned)(~(unsigned)me) & 0xFFFFu;
            sel_n[r] = n;
            unsigned k32 = (unsigned)(me >> 32);
            unsigned u = (k32 & 0x80000000u) ? (k32 & 0x7FFFFFFFu) : ~k32;
            size_t row = ((size_t)b * TOPK + r) * OUTC;
            out[row + 0] = (float)b;
            out[row + OUTC - 1] = __uint_as_float(u);
        }
    }
    __syncthreads();

    // decode feed in ascending flat-index order (gather locality)
    if (tid < TOPK) {
        unsigned n = sel_n[tid];
        int o = 0;
        for (int j = 0; j < TOPK; j++) o += (sel_n[j] < n);
        g_dec[b * TOPK + o] = n | ((unsigned)tid << 16);
    }
}

// ---------------------------------------------------------------------------
// Kernel 2: decode — the R2-proven shape (8 proposals per 512-thread block).
// ---------------------------------------------------------------------------
__global__ __launch_bounds__(512)
void decode_kernel(const float* __restrict__ bbox,
                   const float* __restrict__ im_info,
                   float* __restrict__ out)
{
    const int tid = threadIdx.x;
    const int j = blockIdx.x * 8 + (tid >> 6);
    const int b = blockIdx.y;
    const int k = tid & 63;
    if (j >= TOPK) return;                     // 64-thread groups: warp-uniform

    const unsigned packed = g_dec[b * TOPK + j];
    const int n    = packed & 0xFFFFu;
    const int rank = packed >> 16;

    const int a  = n % 9;
    const int hw = n / 9;
    const float w  = c_aw[a];
    const float h  = c_ah[a];
    const float cx = 8.0f + 16.0f * (float)(hw & 63);
    const float cy = 8.0f + 16.0f * (float)(hw >> 6);

    const float d = __ldcs(&bbox[((size_t)b * 576 + (size_t)a * 64 + k) * HW + hw]);

    const unsigned base = (tid & 31u) & ~3u;
    const float d0 = __shfl_sync(0xFFFFFFFFu, d, base + 0);
    const float d1 = __shfl_sync(0xFFFFFFFFu, d, base + 1);
    const float d2 = __shfl_sync(0xFFFFFFFFu, d, base + 2);
    const float d3 = __shfl_sync(0xFFFFFFFFu, d, base + 3);

    const float xmax = im_info[b * 3 + 1] - 1.0f;
    const float ymax = im_info[b * 3 + 0] - 1.0f;

    const float pcx = d0 * w + cx;
    const float pcy = d1 * h + cy;
    const float pw  = expf(d2) * w;
    const float ph  = expf(d3) * h;

    float v;
    switch (k & 3) {
        case 0: v = fminf(fmaxf(pcx - 0.5f * pw, 0.0f), xmax); break;
        case 1: v = fminf(fmaxf(pcy - 0.5f * ph, 0.0f), ymax); break;
        case 2: v = fminf(fmaxf(pcx + 0.5f * pw, 0.0f), xmax); break;
        default: v = fminf(fmaxf(pcy + 0.5f * ph, 0.0f), ymax); break;
    }

    out[((size_t)b * TOPK + rank) * OUTC + 1 + k] = v;
}

extern "C" void kernel_launch(void* const* d_in, const int* in_sizes, int n_in,
                              void* d_out, int out_size)
{
    const float* scores  = (const float*)d_in[0];  // (32,18,64,64)
    const float* bbox    = (const float*)d_in[1];  // (32,576,64,64)
    const float* im_info = (const float*)d_in[2];  // (32,3)
    float* out = (float*)d_out;                    // (32,300,66)

    topk_kernel<<<dim3(SLICES, BATCH), 512>>>(scores, out);
    decode_kernel<<<dim3((TOPK + 7) / 8, BATCH), 512>>>(bbox, im_info, out);
}

// round 10
// speedup vs baseline: 1.5837x; 1.5722x over previous
#include <cuda_runtime.h>
#include <cstdint>

#define BATCH   32
#define NA      9
#define HW      4096
#define NPROP   (HW*NA)          // 36864
#define NVEC    (NPROP/4)        // 9216 float4 per batch
#define TOPK    300
#define OUTC    66
#define CAP     2048
#define LCAP    1024             // per-CTA staging (expect ~225)
#define SLICES  2                // compact CTAs per batch

// key threshold for score >= 2.25f (~450 candidates/batch expected, 7σ > 300)
#define THR_FAST 0xC0100000u

// Anchor (w,h) table; centers are always (8+16*gx, 8+16*gy)
__constant__ float c_aw[9] = {92.f,184.f,368.f,64.f,128.f,256.f,44.f,88.f,176.f};
__constant__ float c_ah[9] = {48.f,96.f,192.f,64.f,128.f,256.f,88.f,176.f,352.f};

__device__ int                g_cnt[BATCH * 32];   // stride-32: 128B apart
__device__ int                g_done[BATCH * 32];
__device__ unsigned long long g_cand[BATCH * CAP];
__device__ unsigned           g_dec[BATCH * TOPK]; // n | (rank<<16), asc n

__device__ __forceinline__ unsigned f2key(float s) {
    unsigned u = __float_as_uint(s);
    return (u & 0x80000000u) ? ~u : (u | 0x80000000u);
}

// ---------------------------------------------------------------------------
// Kernel 1: compact (64 CTAs) + rank on the last-finishing CTA per batch.
// No spin-waits: the ranking CTA is elected as the LAST compact finisher.
// ---------------------------------------------------------------------------
__global__ __launch_bounds__(1024, 1)
void topk_kernel(const float* __restrict__ scores_in, float* __restrict__ out)
{
    __shared__ unsigned long long buf[LCAP];     // 8 KB  (compact staging)
    __shared__ unsigned long long cand[CAP];     // 16 KB (rank)
    __shared__ unsigned hist[4096];              // 16 KB (fallback only)
    __shared__ unsigned sel_n[TOPK];
    __shared__ unsigned wsum[32], wpre[32];
    __shared__ unsigned s_thr;
    __shared__ int s_cnt, s_base, s_C, s_isrank;

    const int b     = blockIdx.y;
    const int slice = blockIdx.x;
    const int tid   = threadIdx.x;
    const unsigned lane = tid & 31u;
    const int warp  = tid >> 5;

    const float4* sp =
        (const float4*)(scores_in + (size_t)b * 18 * HW + (size_t)NA * HW);

    // ---------------- compact: smem staging, one global RMW ----------------
    if (tid == 0) s_cnt = 0;
    __syncthreads();

    for (int i = slice * 1024 + tid; i < NVEC; i += SLICES * 1024) {
        float4 v = sp[i];
        float vv[4] = {v.x, v.y, v.z, v.w};
        #pragma unroll
        for (int j = 0; j < 4; j++) {
            unsigned k = f2key(vv[j]);
            if (k >= THR_FAST) {
                int idx = 4 * i + j;               // memory order: a*4096 + hw
                int a = idx >> 12, hw = idx & 4095;
                int n = hw * 9 + a;                // jax flat order
                int pos = atomicAdd(&s_cnt, 1);    // smem atomic: cheap
                if (pos < LCAP)
                    buf[pos] = ((unsigned long long)k << 32) | (unsigned)(~n);
            }
        }
    }
    __syncthreads();

    const int cnt = s_cnt;
    if (cnt > LCAP) {
        // staging overflow (benign-impossible): poison count -> exact fallback
        if (tid == 0) atomicAdd(&g_cnt[b * 32], CAP + 1);
    } else {
        if (tid == 0) s_base = atomicAdd(&g_cnt[b * 32], cnt);  // ONE RMW
        __syncthreads();
        for (int i = tid; i < cnt; i += 1024) {
            int pos = s_base + i;
            if (pos < CAP) g_cand[b * CAP + pos] = buf[i];
        }
    }
    __threadfence();                  // publish this CTA's candidate writes
    __syncthreads();
    if (tid == 0) {
        int t = atomicAdd(&g_done[b * 32], 1);
        s_isrank = (t == SLICES - 1); // last finisher ranks this batch
    }
    __syncthreads();
    if (!s_isrank) return;

    // ---------------- rank (elected CTA; all peers already done) ----------
    __threadfence();                  // acquire peers' g_cand writes
    if (tid == 0) s_C = g_cnt[b * 32];
    __syncthreads();
    int C = s_C;
    if (tid == 0) { g_cnt[b * 32] = 0; g_done[b * 32] = 0; }   // replay reset

    if (C >= TOPK && C <= CAP) {
        for (int i = tid; i < C; i += 1024)
            cand[i] = g_cand[b * CAP + i];
        __syncthreads();
    } else {
        // ---- exact fallback: 4096-bin histogram select (1024 threads) ----
        #pragma unroll
        for (int i = tid; i < 4096; i += 1024) hist[i] = 0;
        if (tid == 0) s_cnt = 0;
        __syncthreads();
        #pragma unroll 3
        for (int i = tid; i < NVEC; i += 1024) {
            float4 v = sp[i];
            atomicAdd(&hist[f2key(v.x) >> 20], 1u);
            atomicAdd(&hist[f2key(v.y) >> 20], 1u);
            atomicAdd(&hist[f2key(v.z) >> 20], 1u);
            atomicAdd(&hist[f2key(v.w) >> 20], 1u);
        }
        __syncthreads();
        // suffix scan from the top: thread t owns bins [4095-4t .. 4092-4t]
        const int bhi = 4095 - 4 * tid;
        unsigned h0 = hist[bhi],     h1 = hist[bhi - 1];
        unsigned h2 = hist[bhi - 2], h3 = hist[bhi - 3];
        unsigned s = h0 + h1 + h2 + h3;
        unsigned incl = s;
        #pragma unroll
        for (int o = 1; o < 32; o <<= 1) {
            unsigned v = __shfl_up_sync(0xFFFFFFFFu, incl, o);
            if (lane >= o) incl += v;
        }
        if (lane == 31) wsum[warp] = incl;
        __syncthreads();
        if (warp == 0) {
            unsigned w = wsum[lane];
            unsigned wi = w;
            #pragma unroll
            for (int o = 1; o < 32; o <<= 1) {
                unsigned v = __shfl_up_sync(0xFFFFFFFFu, wi, o);
                if (lane >= o) wi += v;
            }
            wpre[lane] = wi - w;
        }
        __syncthreads();
        {
            unsigned cc = wpre[warp] + (incl - s);   // count above bin bhi
            unsigned hh[4] = {h0, h1, h2, h3};
            #pragma unroll
            for (int j = 0; j < 4; j++) {
                if (cc < TOPK && cc + hh[j] >= TOPK)
                    s_thr = ((unsigned)(bhi - j)) << 20;
                cc += hh[j];
            }
        }
        __syncthreads();
        const unsigned thr = s_thr;
        if (tid == 0) s_cnt = 0;
        __syncthreads();
        #pragma unroll 3
        for (int i = tid; i < NVEC; i += 1024) {
            float4 v = sp[i];
            float vv[4] = {v.x, v.y, v.z, v.w};
            #pragma unroll
            for (int j = 0; j < 4; j++) {
                unsigned k = f2key(vv[j]);
                if (k >= thr) {
                    int idx = 4 * i + j;
                    int a = idx >> 12, hw = idx & 4095;
                    int n = hw * 9 + a;
                    int pos = atomicAdd(&s_cnt, 1);
                    if (pos < CAP)
                        cand[pos] = ((unsigned long long)k << 32) | (unsigned)(~n);
                }
            }
        }
        __syncthreads();
        C = min(s_cnt, CAP);
    }

    // ---- exact rank by counting (unique keys -> jax tie-break preserved) ----
    for (int i = tid; i < C; i += 1024) {
        const unsigned long long me = cand[i];
        int r = 0;
        for (int j = 0; j < C; j++) r += (cand[j] > me);   // smem broadcast
        if (r < TOPK) {
            unsigned n = (unsigned)(~(unsigned)me) & 0xFFFFu;
            sel_n[r] = n;
            unsigned k32 = (unsigned)(me >> 32);
            unsigned u = (k32 & 0x80000000u) ? (k32 & 0x7FFFFFFFu) : ~k32;
            size_t row = ((size_t)b * TOPK + r) * OUTC;
            out[row + 0] = (float)b;
            out[row + OUTC - 1] = __uint_as_float(u);
        }
    }
    __syncthreads();

    // decode feed in ascending flat-index order (gather locality)
    if (tid < TOPK) {
        unsigned n = sel_n[tid];
        int o = 0;
        for (int j = 0; j < TOPK; j++) o += (sel_n[j] < n);
        g_dec[b * TOPK + o] = n | ((unsigned)tid << 16);
    }
}

// ---------------------------------------------------------------------------
// Kernel 2: decode — the proven shape (8 proposals per 512-thread block).
// ---------------------------------------------------------------------------
__global__ __launch_bounds__(512)
void decode_kernel(const float* __restrict__ bbox,
                   const float* __restrict__ im_info,
                   float* __restrict__ out)
{
    const int tid = threadIdx.x;
    const int j = blockIdx.x * 8 + (tid >> 6);
    const int b = blockIdx.y;
    const int k = tid & 63;
    if (j >= TOPK) return;                     // 64-thread groups: warp-uniform

    const unsigned packed = g_dec[b * TOPK + j];
    const int n    = packed & 0xFFFFu;
    const int rank = packed >> 16;

    const int a  = n % 9;
    const int hw = n / 9;
    const float w  = c_aw[a];
    const float h  = c_ah[a];
    const float cx = 8.0f + 16.0f * (float)(hw & 63);
    const float cy = 8.0f + 16.0f * (float)(hw >> 6);

    const float d = __ldcs(&bbox[((size_t)b * 576 + (size_t)a * 64 + k) * HW + hw]);

    const unsigned base = (tid & 31u) & ~3u;
    const float d0 = __shfl_sync(0xFFFFFFFFu, d, base + 0);
    const float d1 = __shfl_sync(0xFFFFFFFFu, d, base + 1);
    const float d2 = __shfl_sync(0xFFFFFFFFu, d, base + 2);
    const float d3 = __shfl_sync(0xFFFFFFFFu, d, base + 3);

    const float xmax = im_info[b * 3 + 1] - 1.0f;
    const float ymax = im_info[b * 3 + 0] - 1.0f;

    const float pcx = d0 * w + cx;
    const float pcy = d1 * h + cy;
    const float pw  = expf(d2) * w;
    const float ph  = expf(d3) * h;

    float v;
    switch (k & 3) {
        case 0: v = fminf(fmaxf(pcx - 0.5f * pw, 0.0f), xmax); break;
        case 1: v = fminf(fmaxf(pcy - 0.5f * ph, 0.0f), ymax); break;
        case 2: v = fminf(fmaxf(pcx + 0.5f * pw, 0.0f), xmax); break;
        default: v = fminf(fmaxf(pcy + 0.5f * ph, 0.0f), ymax); break;
    }

    out[((size_t)b * TOPK + rank) * OUTC + 1 + k] = v;
}

extern "C" void kernel_launch(void* const* d_in, const int* in_sizes, int n_in,
                              void* d_out, int out_size)
{
    const float* scores  = (const float*)d_in[0];  // (32,18,64,64)
    const float* bbox    = (const float*)d_in[1];  // (32,576,64,64)
    const float* im_info = (const float*)d_in[2];  // (32,3)
    float* out = (float*)d_out;                    // (32,300,66)

    topk_kernel<<<dim3(SLICES, BATCH), 1024>>>(scores, out);
    decode_kernel<<<dim3((TOPK + 7) / 8, BATCH), 512>>>(bbox, im_info, out);
}

// round 12
// speedup vs baseline: 1.7246x; 1.0890x over previous
#include <cuda_runtime.h>
#include <cstdint>

#define BATCH   32
#define NA      9
#define HW      4096
#define NPROP   (HW*NA)          // 36864
#define NVEC    (NPROP/4)        // 9216 float4 per batch
#define TOPK    300
#define OUTC    66
#define CAP     2048
#define LCAP    1024             // per-CTA staging (expect ~115)
#define SLICES  4                // compact CTAs per batch

// key threshold for score >= 2.25f (~450 candidates/batch expected, 7σ > 300)
#define THR_FAST 0xC0100000u

// Anchor (w,h) table; centers are always (8+16*gx, 8+16*gy)
__constant__ float c_aw[9] = {92.f,184.f,368.f,64.f,128.f,256.f,44.f,88.f,176.f};
__constant__ float c_ah[9] = {48.f,96.f,192.f,64.f,128.f,256.f,88.f,176.f,352.f};

__device__ int                g_cnt[BATCH * 32];   // stride-32: 128B apart
__device__ int                g_done[BATCH * 32];
__device__ unsigned long long g_cand[BATCH * CAP];
__device__ unsigned           g_dec[BATCH * TOPK]; // n | (rank<<16), asc n

__device__ __forceinline__ unsigned f2key(float s) {
    unsigned u = __float_as_uint(s);
    return (u & 0x80000000u) ? ~u : (u | 0x80000000u);
}

// ---------------------------------------------------------------------------
// Kernel 1: compact (128 CTAs) + rank on the last-finishing CTA per batch.
// No spin-waits: the ranking CTA is elected as the LAST compact finisher.
// ---------------------------------------------------------------------------
__global__ __launch_bounds__(1024, 1)
void topk_kernel(const float* __restrict__ scores_in, float* __restrict__ out)
{
    __shared__ unsigned long long buf[LCAP];       // 8 KB  (compact staging)
    __shared__ unsigned long long cand[CAP + 16];  // 16 KB (rank, padded)
    __shared__ unsigned hist[4096];                // 16 KB (fallback only)
    __shared__ unsigned sel_n[TOPK + 8];           // padded for unroll
    __shared__ unsigned wsum[32], wpre[32];
    __shared__ unsigned s_thr;
    __shared__ int s_cnt, s_base, s_C, s_isrank;

    const int b     = blockIdx.y;
    const int slice = blockIdx.x;
    const int tid   = threadIdx.x;
    const unsigned lane = tid & 31u;
    const int warp  = tid >> 5;

    const float4* sp =
        (const float4*)(scores_in + (size_t)b * 18 * HW + (size_t)NA * HW);

    // ---------------- compact: smem staging, one global RMW ----------------
    if (tid == 0) s_cnt = 0;
    __syncthreads();

    for (int i = slice * 1024 + tid; i < NVEC; i += SLICES * 1024) {
        float4 v = sp[i];
        float vv[4] = {v.x, v.y, v.z, v.w};
        #pragma unroll
        for (int j = 0; j < 4; j++) {
            unsigned k = f2key(vv[j]);
            if (k >= THR_FAST) {
                int idx = 4 * i + j;               // memory order: a*4096 + hw
                int a = idx >> 12, hw = idx & 4095;
                int n = hw * 9 + a;                // jax flat order
                int pos = atomicAdd(&s_cnt, 1);    // smem atomic: cheap
                if (pos < LCAP)
                    buf[pos] = ((unsigned long long)k << 32) | (unsigned)(~n);
            }
        }
    }
    __syncthreads();

    const int cnt = s_cnt;
    if (cnt > LCAP) {
        // staging overflow (benign-impossible): poison count -> exact fallback
        if (tid == 0) atomicAdd(&g_cnt[b * 32], CAP + 1);
    } else {
        if (tid == 0) s_base = atomicAdd(&g_cnt[b * 32], cnt);  // ONE RMW
        __syncthreads();
        for (int i = tid; i < cnt; i += 1024) {
            int pos = s_base + i;
            if (pos < CAP) g_cand[b * CAP + pos] = buf[i];
        }
    }
    __threadfence();                  // publish this CTA's candidate writes
    __syncthreads();
    if (tid == 0) {
        int t = atomicAdd(&g_done[b * 32], 1);
        s_isrank = (t == SLICES - 1); // last finisher ranks this batch
    }
    __syncthreads();
    if (!s_isrank) return;

    // ---------------- rank (elected CTA; all peers already done) ----------
    __threadfence();                  // acquire peers' g_cand writes
    if (tid == 0) s_C = g_cnt[b * 32];
    __syncthreads();
    int C = s_C;
    if (tid == 0) { g_cnt[b * 32] = 0; g_done[b * 32] = 0; }   // replay reset

    if (C >= TOPK && C <= CAP) {
        for (int i = tid; i < C; i += 1024)
            cand[i] = g_cand[b * CAP + i];
    } else {
        // ---- exact fallback: 4096-bin histogram select (1024 threads) ----
        #pragma unroll
        for (int i = tid; i < 4096; i += 1024) hist[i] = 0;
        if (tid == 0) s_cnt = 0;
        __syncthreads();
        #pragma unroll 3
        for (int i = tid; i < NVEC; i += 1024) {
            float4 v = sp[i];
            atomicAdd(&hist[f2key(v.x) >> 20], 1u);
            atomicAdd(&hist[f2key(v.y) >> 20], 1u);
            atomicAdd(&hist[f2key(v.z) >> 20], 1u);
            atomicAdd(&hist[f2key(v.w) >> 20], 1u);
        }
        __syncthreads();
        // suffix scan from the top: thread t owns bins [4095-4t .. 4092-4t]
        const int bhi = 4095 - 4 * tid;
        unsigned h0 = hist[bhi],     h1 = hist[bhi - 1];
        unsigned h2 = hist[bhi - 2], h3 = hist[bhi - 3];
        unsigned s = h0 + h1 + h2 + h3;
        unsigned incl = s;
        #pragma unroll
        for (int o = 1; o < 32; o <<= 1) {
            unsigned v = __shfl_up_sync(0xFFFFFFFFu, incl, o);
            if (lane >= o) incl += v;
        }
        if (lane == 31) wsum[warp] = incl;
        __syncthreads();
        if (warp == 0) {
            unsigned w = wsum[lane];
            unsigned wi = w;
            #pragma unroll
            for (int o = 1; o < 32; o <<= 1) {
                unsigned v = __shfl_up_sync(0xFFFFFFFFu, wi, o);
                if (lane >= o) wi += v;
            }
            wpre[lane] = wi - w;
        }
        __syncthreads();
        {
            unsigned cc = wpre[warp] + (incl - s);   // count above bin bhi
            unsigned hh[4] = {h0, h1, h2, h3};
            #pragma unroll
            for (int j = 0; j < 4; j++) {
                if (cc < TOPK && cc + hh[j] >= TOPK)
                    s_thr = ((unsigned)(bhi - j)) << 20;
                cc += hh[j];
            }
        }
        __syncthreads();
        const unsigned thr = s_thr;
        if (tid == 0) s_cnt = 0;
        __syncthreads();
        #pragma unroll 3
        for (int i = tid; i < NVEC; i += 1024) {
            float4 v = sp[i];
            float vv[4] = {v.x, v.y, v.z, v.w};
            #pragma unroll
            for (int j = 0; j < 4; j++) {
                unsigned k = f2key(vv[j]);
                if (k >= thr) {
                    int idx = 4 * i + j;
                    int a = idx >> 12, hw = idx & 4095;
                    int n = hw * 9 + a;
                    int pos = atomicAdd(&s_cnt, 1);
                    if (pos < CAP)
                        cand[pos] = ((unsigned long long)k << 32) | (unsigned)(~n);
                }
            }
        }
        __syncthreads();
        C = min(s_cnt, CAP);
    }
    // zero-pad so the unrolled rank loop can overrun harmlessly
    if (tid < 16) cand[C + tid] = 0ull;
    __syncthreads();

    // ---- exact rank by counting, 16x unrolled (16 independent LDS in flight)
    for (int i = tid; i < C; i += 1024) {
        const unsigned long long me = cand[i];
        int r = 0;
        for (int j = 0; j < C; j += 16) {
            #pragma unroll
            for (int u = 0; u < 16; u++)
                r += (cand[j + u] > me);           // broadcast reads
        }
        if (r < TOPK) {
            unsigned n = (unsigned)(~(unsigned)me);
            sel_n[r] = n;
            unsigned k32 = (unsigned)(me >> 32);
            unsigned u = (k32 & 0x80000000u) ? (k32 & 0x7FFFFFFFu) : ~k32;
            size_t row = ((size_t)b * TOPK + r) * OUTC;
            out[row + 0] = (float)b;
            out[row + OUTC - 1] = __uint_as_float(u);
        }
    }
    if (tid < 8) sel_n[TOPK + tid] = 0xFFFFFFFFu;  // pad: never counts as less
    __syncthreads();

    // decode feed in ascending flat-index order (gather locality), unrolled
    if (tid < TOPK) {
        unsigned n = sel_n[tid];
        int o = 0;
        for (int j = 0; j < TOPK + 4; j += 4) {
            #pragma unroll
            for (int u = 0; u < 4; u++)
                o += (sel_n[j + u] < n);
        }
        g_dec[b * TOPK + o] = n | ((unsigned)tid << 16);
    }
}

// ---------------------------------------------------------------------------
// Kernel 2: decode — the proven shape (8 proposals per 512-thread block).
// ---------------------------------------------------------------------------
__global__ __launch_bounds__(512)
void decode_kernel(const float* __restrict__ bbox,
                   const float* __restrict__ im_info,
                   float* __restrict__ out)
{
    const int tid = threadIdx.x;
    const int j = blockIdx.x * 8 + (tid >> 6);
    const int b = blockIdx.y;
    const int k = tid & 63;
    if (j >= TOPK) return;                     // 64-thread groups: warp-uniform

    const unsigned packed = g_dec[b * TOPK + j];
    const int n    = packed & 0xFFFFu;
    const int rank = packed >> 16;

    const int a  = n % 9;
    const int hw = n / 9;
    const float w  = c_aw[a];
    const float h  = c_ah[a];
    const float cx = 8.0f + 16.0f * (float)(hw & 63);
    const float cy = 8.0f + 16.0f * (float)(hw >> 6);

    const float d = __ldcs(&bbox[((size_t)b * 576 + (size_t)a * 64 + k) * HW + hw]);

    const unsigned base = (tid & 31u) & ~3u;
    const float d0 = __shfl_sync(0xFFFFFFFFu, d, base + 0);
    const float d1 = __shfl_sync(0xFFFFFFFFu, d, base + 1);
    const float d2 = __shfl_sync(0xFFFFFFFFu, d, base + 2);
    const float d3 = __shfl_sync(0xFFFFFFFFu, d, base + 3);

    const float xmax = im_info[b * 3 + 1] - 1.0f;
    const float ymax = im_info[b * 3 + 0] - 1.0f;

    const float pcx = d0 * w + cx;
    const float pcy = d1 * h + cy;
    const float pw  = expf(d2) * w;
    const float ph  = expf(d3) * h;

    float v;
    switch (k & 3) {
        case 0: v = fminf(fmaxf(pcx - 0.5f * pw, 0.0f), xmax); break;
        case 1: v = fminf(fmaxf(pcy - 0.5f * ph, 0.0f), ymax); break;
        case 2: v = fminf(fmaxf(pcx + 0.5f * pw, 0.0f), xmax); break;
        default: v = fminf(fmaxf(pcy + 0.5f * ph, 0.0f), ymax); break;
    }

    out[((size_t)b * TOPK + rank) * OUTC + 1 + k] = v;
}

extern "C" void kernel_launch(void* const* d_in, const int* in_sizes, int n_in,
                              void* d_out, int out_size)
{
    const float* scores  = (const float*)d_in[0];  // (32,18,64,64)
    const float* bbox    = (const float*)d_in[1];  // (32,576,64,64)
    const float* im_info = (const float*)d_in[2];  // (32,3)
    float* out = (float*)d_out;                    // (32,300,66)

    topk_kernel<<<dim3(SLICES, BATCH), 1024>>>(scores, out);
    decode_kernel<<<dim3((TOPK + 7) / 8, BATCH), 512>>>(bbox, im_info, out);
}